// round 2
// baseline (speedup 1.0000x reference)
#include <cuda_runtime.h>
#include <math.h>

#define NN 100000   // nodes
#define DD 256      // dim
#define EE 200000   // edges
#define BB 50000    // query pairs
#define FF 64       // pairwise feature dim
#define HH 256      // MLP hidden
#define WDEC 1e-6f
#define NW 12       // warps per block in pair kernel

// scratch: updated tables 1..3 (table 0 == rp0, untouched)
__device__ float g_new[3][(size_t)NN * DD];

// ---------------------------------------------------------------------------
// Kernel 1: new_i = decay^i * rp_i  (i = 1..3 -> g_new[0..2])
// ---------------------------------------------------------------------------
__global__ void init_kernel(const float* __restrict__ rp1,
                            const float* __restrict__ rp2,
                            const float* __restrict__ rp3,
                            const float* __restrict__ times,
                            const float* __restrict__ now_time)
{
    const int layer = blockIdx.y;  // 0,1,2 -> tables 1,2,3
    const size_t per4 = (size_t)NN * DD / 4;
    size_t i = (size_t)blockIdx.x * blockDim.x + threadIdx.x;
    if (i >= per4) return;

    float nt = __ldg(&times[EE - 1]);
    float decay = expf(-WDEC * (nt - __ldg(now_time)));
    float s = decay;
    if (layer == 1) s = decay * decay;
    else if (layer == 2) s = decay * decay * decay;

    const float4* src = (const float4*)(layer == 0 ? rp1 : (layer == 1 ? rp2 : rp3));
    float4 v = __ldg(&src[i]);
    v.x *= s; v.y *= s; v.z *= s; v.w *= s;
    reinterpret_cast<float4*>(g_new[layer])[i] = v;
}

// ---------------------------------------------------------------------------
// Kernel 2: scatter-add. One warp per (edge, layer, direction).
//   new_i[node_w] += (decay^(i-1) * tw_e) * rp_{i-1}[node_r]
// All reads hit the ORIGINAL input tables (matches reference: each layer uses
// pre-update rps[i-1]).
// ---------------------------------------------------------------------------
__global__ void scatter_kernel(const float* __restrict__ rp0,
                               const float* __restrict__ rp1,
                               const float* __restrict__ rp2,
                               const float* __restrict__ times,
                               const float* __restrict__ now_time,
                               const int* __restrict__ src_ids,
                               const int* __restrict__ dst_ids)
{
    int wid = (int)(((long long)blockIdx.x * blockDim.x + threadIdx.x) >> 5);
    int lane = threadIdx.x & 31;
    if (wid >= EE * 6) return;

    int e = wid / 6;
    int r = wid - e * 6;
    int layer = r >> 1;   // source table index (0..2); dest = g_new[layer]
    int dir = r & 1;

    float nt = __ldg(&times[EE - 1]);
    float decay = expf(-WDEC * (nt - __ldg(now_time)));
    float coef = expf(-WDEC * (nt - __ldg(&times[e])));   // tw_e
    if (layer == 1) coef *= decay;
    else if (layer == 2) coef *= decay * decay;

    int s = __ldg(&src_ids[e]);
    int d = __ldg(&dst_ids[e]);
    int node_w = dir ? d : s;
    int node_r = dir ? s : d;

    const float* srct = (layer == 0) ? rp0 : ((layer == 1) ? rp1 : rp2);
    const float4* rv = (const float4*)(srct + (size_t)node_r * DD);
    float* wb = g_new[layer] + (size_t)node_w * DD;

#pragma unroll
    for (int k = 0; k < 2; k++) {
        float4 v = __ldg(&rv[lane + 32 * k]);
        v.x *= coef; v.y *= coef; v.z *= coef; v.w *= coef;
        float* addr = wb + 4 * (lane + 32 * k);
        asm volatile("red.global.add.v4.f32 [%0], {%1,%2,%3,%4};"
                     :: "l"(addr), "f"(v.x), "f"(v.y), "f"(v.z), "f"(v.w)
                     : "memory");
    }
}

// ---------------------------------------------------------------------------
// Kernel 3: per-pair gather + 8x8 Gram + log1p + MLP(64->256 relu ->64).
// One warp per pair; weights staged in shared; persistent grid.
// ---------------------------------------------------------------------------
__global__ void __launch_bounds__(NW * 32, 1)
pair_kernel(const float* __restrict__ rp0,
            const float* __restrict__ w1, const float* __restrict__ b1,
            const float* __restrict__ w2, const float* __restrict__ b2,
            const int* __restrict__ q_src, const int* __restrict__ q_dst,
            float* __restrict__ out)
{
    extern __shared__ float sm[];
    float* s_w1 = sm;                      // 64*256
    float* s_w2 = s_w1 + FF * HH;          // 256*64
    float* s_b1 = s_w2 + HH * FF;          // 256
    float* s_b2 = s_b1 + HH;               // 64
    float* s_scr = s_b2 + FF;              // NW * (256 h + 64 feat + 64 gram-pad)

    for (int i = threadIdx.x; i < FF * HH; i += blockDim.x) {
        s_w1[i] = w1[i];
        s_w2[i] = w2[i];
    }
    for (int i = threadIdx.x; i < HH; i += blockDim.x) s_b1[i] = b1[i];
    for (int i = threadIdx.x; i < FF; i += blockDim.x) s_b2[i] = b2[i];
    __syncthreads();

    const int warp = threadIdx.x >> 5;
    const int lane = threadIdx.x & 31;
    float* s_h    = s_scr + warp * (HH + FF + 64);
    float* s_feat = s_h + HH;
    float* s_gram = s_feat + FF;

    const int gw = blockIdx.x * NW + warp;
    const int stride = gridDim.x * NW;

    for (int p = gw; p < BB; p += stride) {
        int qs = __ldg(&q_src[p]);
        int qd = __ldg(&q_dst[p]);

        const float* vp[8];
        vp[0] = rp0      + (size_t)qs * DD;
        vp[1] = g_new[0] + (size_t)qs * DD;
        vp[2] = g_new[1] + (size_t)qs * DD;
        vp[3] = g_new[2] + (size_t)qs * DD;
        vp[4] = rp0      + (size_t)qd * DD;
        vp[5] = g_new[0] + (size_t)qd * DD;
        vp[6] = g_new[1] + (size_t)qd * DD;
        vp[7] = g_new[2] + (size_t)qd * DD;

        // --- Gram: 36 upper-triangular dot products over D=256 ---
        float acc[36];
#pragma unroll
        for (int t = 0; t < 36; t++) acc[t] = 0.f;

#pragma unroll
        for (int c = 0; c < 2; c++) {
            float4 v[8];
#pragma unroll
            for (int j = 0; j < 8; j++)
                v[j] = __ldg(((const float4*)vp[j]) + lane + 32 * c);
            int t = 0;
#pragma unroll
            for (int a = 0; a < 8; a++)
#pragma unroll
                for (int b = a; b < 8; b++, t++)
                    acc[t] += v[a].x * v[b].x + v[a].y * v[b].y
                            + v[a].z * v[b].z + v[a].w * v[b].w;
        }

#pragma unroll
        for (int t = 0; t < 36; t++) {
#pragma unroll
            for (int off = 16; off; off >>= 1)
                acc[t] += __shfl_xor_sync(0xffffffffu, acc[t], off);
            if (lane == 0) s_gram[t] = acc[t];
        }
        __syncwarp();

        // feat[f] = log1p(max(gram[p,q],0)), f = p*8+q, gram symmetric
#pragma unroll
        for (int f0 = 0; f0 < 2; f0++) {
            int f = lane * 2 + f0;
            int a = f >> 3, b = f & 7;
            int lo = a < b ? a : b;
            int hi = a < b ? b : a;
            int idx = lo * 8 - (lo * (lo - 1)) / 2 + (hi - lo);
            float g = s_gram[idx];
            s_feat[f] = log1pf(fmaxf(g, 0.f));
        }
        __syncwarp();

        // --- layer 1: h = relu(feat @ w1 + b1); lane owns columns 8l..8l+7 ---
        float4 a0 = make_float4(0.f, 0.f, 0.f, 0.f);
        float4 a1 = make_float4(0.f, 0.f, 0.f, 0.f);
#pragma unroll
        for (int f = 0; f < FF; f++) {
            float x = s_feat[f];  // uniform-address broadcast
            float4 wA = *(const float4*)&s_w1[f * HH + 8 * lane];
            float4 wB = *(const float4*)&s_w1[f * HH + 8 * lane + 4];
            a0.x += x * wA.x; a0.y += x * wA.y; a0.z += x * wA.z; a0.w += x * wA.w;
            a1.x += x * wB.x; a1.y += x * wB.y; a1.z += x * wB.z; a1.w += x * wB.w;
        }
        {
            float4 bA = *(const float4*)&s_b1[8 * lane];
            float4 bB = *(const float4*)&s_b1[8 * lane + 4];
            a0.x = fmaxf(a0.x + bA.x, 0.f); a0.y = fmaxf(a0.y + bA.y, 0.f);
            a0.z = fmaxf(a0.z + bA.z, 0.f); a0.w = fmaxf(a0.w + bA.w, 0.f);
            a1.x = fmaxf(a1.x + bB.x, 0.f); a1.y = fmaxf(a1.y + bB.y, 0.f);
            a1.z = fmaxf(a1.z + bB.z, 0.f); a1.w = fmaxf(a1.w + bB.w, 0.f);
            *(float4*)&s_h[8 * lane] = a0;
            *(float4*)&s_h[8 * lane + 4] = a1;
        }
        __syncwarp();

        // --- layer 2: out = h @ w2 + b2; lane owns output columns 2l, 2l+1 ---
        float o0 = s_b2[2 * lane];
        float o1 = s_b2[2 * lane + 1];
#pragma unroll 8
        for (int k = 0; k < HH; k++) {
            float hk = s_h[k];  // broadcast
            float2 w = *(const float2*)&s_w2[k * FF + 2 * lane];
            o0 += hk * w.x;
            o1 += hk * w.y;
        }
        *(float2*)&out[(size_t)p * FF + 2 * lane] = make_float2(o0, o1);
        __syncwarp();
    }
}

// ---------------------------------------------------------------------------
extern "C" void kernel_launch(void* const* d_in, const int* in_sizes, int n_in,
                              void* d_out, int out_size)
{
    const float* rp0      = (const float*)d_in[0];
    const float* rp1      = (const float*)d_in[1];
    const float* rp2      = (const float*)d_in[2];
    const float* rp3      = (const float*)d_in[3];
    const float* times    = (const float*)d_in[4];
    const float* now_time = (const float*)d_in[5];
    const float* w1       = (const float*)d_in[6];
    const float* b1       = (const float*)d_in[7];
    const float* w2       = (const float*)d_in[8];
    const float* b2       = (const float*)d_in[9];
    const int*   src_ids  = (const int*)d_in[10];
    const int*   dst_ids  = (const int*)d_in[11];
    const int*   q_src    = (const int*)d_in[12];
    const int*   q_dst    = (const int*)d_in[13];
    float*       out      = (float*)d_out;

    // 1) decayed copies of tables 1..3
    {
        size_t per4 = (size_t)NN * DD / 4;          // 6,400,000 float4
        dim3 grid((unsigned)((per4 + 255) / 256), 3);
        init_kernel<<<grid, 256>>>(rp1, rp2, rp3, times, now_time);
    }
    // 2) scatter: one warp per (edge, layer, dir) = 1.2M warps
    {
        long long warps = (long long)EE * 6;
        int blocks = (int)((warps * 32 + 255) / 256);
        scatter_kernel<<<blocks, 256>>>(rp0, rp1, rp2, times, now_time,
                                        src_ids, dst_ids);
    }
    // 3) pairwise features + MLP (persistent grid, weights in shared)
    {
        int smem = (FF * HH + HH * FF + HH + FF + NW * (HH + FF + 64)) * 4;
        cudaFuncSetAttribute(pair_kernel,
                             cudaFuncAttributeMaxDynamicSharedMemorySize, smem);
        pair_kernel<<<152, NW * 32, smem>>>(rp0, w1, b1, w2, b2,
                                            q_src, q_dst, out);
    }
}

// round 3
// speedup vs baseline: 1.2245x; 1.2245x over previous
#include <cuda_runtime.h>
#include <math.h>

#define NN 100000   // nodes
#define DD 256      // dim
#define EE 200000   // edges
#define BB 50000    // query pairs
#define FF 64       // pairwise feature dim
#define HH 256      // MLP hidden
#define WDEC 1e-6f
#define NW 16       // warps per block in pair kernel
#define NE (2 * EE) // total (edge,dir) entries

// output tables 1..3 (table 0 == rp0, untouched)
__device__ float g_new[3][(size_t)NN * DD];
// counting-sort scratch
__device__ int   g_cnt[NN + 1];
__device__ int   g_off[NN + 1];
__device__ int   g_cur[NN];
__device__ int   g_other[NE];
__device__ float g_coef[NE];

// ---------------------------------------------------------------------------
// counting sort of (edge,dir) entries by destination node
// ---------------------------------------------------------------------------
__global__ void zero_kernel()
{
    int i = blockIdx.x * blockDim.x + threadIdx.x;
    if (i <= NN) g_cnt[i] = 0;
}

__global__ void count_kernel(const int* __restrict__ src_ids,
                             const int* __restrict__ dst_ids)
{
    int i = blockIdx.x * blockDim.x + threadIdx.x;
    if (i >= NE) return;
    int e = i >> 1, dir = i & 1;
    int node = dir ? __ldg(&dst_ids[e]) : __ldg(&src_ids[e]);
    atomicAdd(&g_cnt[node], 1);
}

__global__ void scan_kernel()
{
    __shared__ int s[1024];
    const int t = threadIdx.x;
    const int CH = (NN + 1023) / 1024;
    int begin = t * CH;
    int end = begin + CH; if (end > NN) end = NN;
    int sum = 0;
    for (int i = begin; i < end; i++) sum += g_cnt[i];
    s[t] = sum;
    __syncthreads();
#pragma unroll
    for (int off = 1; off < 1024; off <<= 1) {
        int v = (t >= off) ? s[t - off] : 0;
        __syncthreads();
        s[t] += v;
        __syncthreads();
    }
    int run = s[t] - sum;   // exclusive prefix for this thread's range
    for (int i = begin; i < end; i++) {
        int c = g_cnt[i];
        g_off[i] = run;
        g_cur[i] = run;
        run += c;
    }
    if (t == 1023) g_off[NN] = run;   // total = NE
}

__global__ void place_kernel(const int* __restrict__ src_ids,
                             const int* __restrict__ dst_ids,
                             const float* __restrict__ times)
{
    int i = blockIdx.x * blockDim.x + threadIdx.x;
    if (i >= NE) return;
    int e = i >> 1, dir = i & 1;
    int s = __ldg(&src_ids[e]);
    int d = __ldg(&dst_ids[e]);
    int node  = dir ? d : s;
    int other = dir ? s : d;
    float nt = __ldg(&times[EE - 1]);
    float tw = expf(-WDEC * (nt - __ldg(&times[e])));
    int pos = atomicAdd(&g_cur[node], 1);
    g_other[pos] = other;
    g_coef[pos]  = tw;
}

// ---------------------------------------------------------------------------
// Fused update: one warp per (node, table).
//   g_new[t][n] = decay^{t+1} * rp_{t+1}[n] + decay^t * sum_e tw_e * rp_t[other_e]
// ---------------------------------------------------------------------------
__global__ void __launch_bounds__(256)
gather_kernel(const float* __restrict__ rp0, const float* __restrict__ rp1,
              const float* __restrict__ rp2, const float* __restrict__ rp3,
              const float* __restrict__ times,
              const float* __restrict__ now_time)
{
    const int t = blockIdx.y;                      // table 0..2 -> g_new index
    const int warp = threadIdx.x >> 5;
    const int lane = threadIdx.x & 31;
    const int n = blockIdx.x * 8 + warp;
    if (n >= NN) return;

    float nt = __ldg(&times[EE - 1]);
    float decay = expf(-WDEC * (nt - __ldg(now_time)));
    float sbase, ssrc;
    if (t == 0)      { ssrc = 1.f;            sbase = decay; }
    else if (t == 1) { ssrc = decay;          sbase = decay * decay; }
    else             { ssrc = decay * decay;  sbase = decay * decay * decay; }

    const float* srct  = (t == 0) ? rp0 : ((t == 1) ? rp1 : rp2);
    const float* baset = (t == 0) ? rp1 : ((t == 1) ? rp2 : rp3);

    const float4* bp = (const float4*)(baset + (size_t)n * DD);
    float4 a0 = __ldg(&bp[lane]);
    float4 a1 = __ldg(&bp[lane + 32]);
    a0.x *= sbase; a0.y *= sbase; a0.z *= sbase; a0.w *= sbase;
    a1.x *= sbase; a1.y *= sbase; a1.z *= sbase; a1.w *= sbase;

    int start = __ldg(&g_off[n]);
    int end   = __ldg(&g_off[n + 1]);
    for (int j = start; j < end; j++) {
        int other = __ldg(&g_other[j]);
        float c = __ldg(&g_coef[j]) * ssrc;
        const float4* sp = (const float4*)(srct + (size_t)other * DD);
        float4 v0 = __ldg(&sp[lane]);
        float4 v1 = __ldg(&sp[lane + 32]);
        a0.x += c * v0.x; a0.y += c * v0.y; a0.z += c * v0.z; a0.w += c * v0.w;
        a1.x += c * v1.x; a1.y += c * v1.y; a1.z += c * v1.z; a1.w += c * v1.w;
    }

    float4* wp = (float4*)(g_new[t] + (size_t)n * DD);
    wp[lane] = a0;
    wp[lane + 32] = a1;
}

// ---------------------------------------------------------------------------
// Per-pair gather + 8x8 Gram + log1p + MLP(64->256 relu ->64).
// One warp per pair; weights staged in shared; persistent grid.
// ---------------------------------------------------------------------------
__global__ void __launch_bounds__(NW * 32, 1)
pair_kernel(const float* __restrict__ rp0,
            const float* __restrict__ w1, const float* __restrict__ b1,
            const float* __restrict__ w2, const float* __restrict__ b2,
            const int* __restrict__ q_src, const int* __restrict__ q_dst,
            float* __restrict__ out)
{
    extern __shared__ float sm[];
    float* s_w1 = sm;                      // 64*256
    float* s_w2 = s_w1 + FF * HH;          // 256*64
    float* s_b1 = s_w2 + HH * FF;          // 256
    float* s_b2 = s_b1 + HH;               // 64
    float* s_scr = s_b2 + FF;              // NW * (256 h + 64 feat + 64 gram)

    for (int i = threadIdx.x; i < FF * HH; i += blockDim.x) {
        s_w1[i] = w1[i];
        s_w2[i] = w2[i];
    }
    for (int i = threadIdx.x; i < HH; i += blockDim.x) s_b1[i] = b1[i];
    for (int i = threadIdx.x; i < FF; i += blockDim.x) s_b2[i] = b2[i];
    __syncthreads();

    const int warp = threadIdx.x >> 5;
    const int lane = threadIdx.x & 31;
    float* s_h    = s_scr + warp * (HH + FF + 64);
    float* s_feat = s_h + HH;
    float* s_gram = s_feat + FF;

    const int gw = blockIdx.x * NW + warp;
    const int stride = gridDim.x * NW;

    for (int p = gw; p < BB; p += stride) {
        int qs = __ldg(&q_src[p]);
        int qd = __ldg(&q_dst[p]);

        const float* vp[8];
        vp[0] = rp0      + (size_t)qs * DD;
        vp[1] = g_new[0] + (size_t)qs * DD;
        vp[2] = g_new[1] + (size_t)qs * DD;
        vp[3] = g_new[2] + (size_t)qs * DD;
        vp[4] = rp0      + (size_t)qd * DD;
        vp[5] = g_new[0] + (size_t)qd * DD;
        vp[6] = g_new[1] + (size_t)qd * DD;
        vp[7] = g_new[2] + (size_t)qd * DD;

        // --- Gram: 36 upper-triangular dot products over D=256 ---
        float acc[36];
#pragma unroll
        for (int t = 0; t < 36; t++) acc[t] = 0.f;

#pragma unroll
        for (int c = 0; c < 2; c++) {
            float4 v[8];
#pragma unroll
            for (int j = 0; j < 8; j++)
                v[j] = __ldg(((const float4*)vp[j]) + lane + 32 * c);
            int t = 0;
#pragma unroll
            for (int a = 0; a < 8; a++)
#pragma unroll
                for (int b = a; b < 8; b++, t++)
                    acc[t] += v[a].x * v[b].x + v[a].y * v[b].y
                            + v[a].z * v[b].z + v[a].w * v[b].w;
        }

#pragma unroll
        for (int t = 0; t < 36; t++) {
#pragma unroll
            for (int off = 16; off; off >>= 1)
                acc[t] += __shfl_xor_sync(0xffffffffu, acc[t], off);
            if (lane == 0) s_gram[t] = acc[t];
        }
        __syncwarp();

        // feat[f] = log1p(max(gram[a,b],0)), f = a*8+b, gram symmetric
#pragma unroll
        for (int f0 = 0; f0 < 2; f0++) {
            int f = lane * 2 + f0;
            int a = f >> 3, b = f & 7;
            int lo = a < b ? a : b;
            int hi = a < b ? b : a;
            int idx = lo * 8 - (lo * (lo - 1)) / 2 + (hi - lo);
            float g = s_gram[idx];
            s_feat[f] = log1pf(fmaxf(g, 0.f));
        }
        __syncwarp();

        // --- layer 1: h = relu(feat @ w1 + b1); lane owns columns 8l..8l+7 ---
        float4 a0 = make_float4(0.f, 0.f, 0.f, 0.f);
        float4 a1 = make_float4(0.f, 0.f, 0.f, 0.f);
#pragma unroll
        for (int f = 0; f < FF; f++) {
            float x = s_feat[f];  // uniform-address broadcast
            float4 wA = *(const float4*)&s_w1[f * HH + 8 * lane];
            float4 wB = *(const float4*)&s_w1[f * HH + 8 * lane + 4];
            a0.x += x * wA.x; a0.y += x * wA.y; a0.z += x * wA.z; a0.w += x * wA.w;
            a1.x += x * wB.x; a1.y += x * wB.y; a1.z += x * wB.z; a1.w += x * wB.w;
        }
        {
            float4 bA = *(const float4*)&s_b1[8 * lane];
            float4 bB = *(const float4*)&s_b1[8 * lane + 4];
            a0.x = fmaxf(a0.x + bA.x, 0.f); a0.y = fmaxf(a0.y + bA.y, 0.f);
            a0.z = fmaxf(a0.z + bA.z, 0.f); a0.w = fmaxf(a0.w + bA.w, 0.f);
            a1.x = fmaxf(a1.x + bB.x, 0.f); a1.y = fmaxf(a1.y + bB.y, 0.f);
            a1.z = fmaxf(a1.z + bB.z, 0.f); a1.w = fmaxf(a1.w + bB.w, 0.f);
            *(float4*)&s_h[8 * lane] = a0;
            *(float4*)&s_h[8 * lane + 4] = a1;
        }
        __syncwarp();

        // --- layer 2: out = h @ w2 + b2; lane owns output columns 2l, 2l+1 ---
        float o0 = s_b2[2 * lane];
        float o1 = s_b2[2 * lane + 1];
#pragma unroll 8
        for (int k = 0; k < HH; k++) {
            float hk = s_h[k];  // broadcast
            float2 w = *(const float2*)&s_w2[k * FF + 2 * lane];
            o0 += hk * w.x;
            o1 += hk * w.y;
        }
        *(float2*)&out[(size_t)p * FF + 2 * lane] = make_float2(o0, o1);
        __syncwarp();
    }
}

// ---------------------------------------------------------------------------
extern "C" void kernel_launch(void* const* d_in, const int* in_sizes, int n_in,
                              void* d_out, int out_size)
{
    const float* rp0      = (const float*)d_in[0];
    const float* rp1      = (const float*)d_in[1];
    const float* rp2      = (const float*)d_in[2];
    const float* rp3      = (const float*)d_in[3];
    const float* times    = (const float*)d_in[4];
    const float* now_time = (const float*)d_in[5];
    const float* w1       = (const float*)d_in[6];
    const float* b1       = (const float*)d_in[7];
    const float* w2       = (const float*)d_in[8];
    const float* b2       = (const float*)d_in[9];
    const int*   src_ids  = (const int*)d_in[10];
    const int*   dst_ids  = (const int*)d_in[11];
    const int*   q_src    = (const int*)d_in[12];
    const int*   q_dst    = (const int*)d_in[13];
    float*       out      = (float*)d_out;

    // counting sort of (edge,dir) by destination node
    zero_kernel<<<(NN + 256) / 256, 256>>>();
    count_kernel<<<(NE + 255) / 256, 256>>>(src_ids, dst_ids);
    scan_kernel<<<1, 1024>>>();
    place_kernel<<<(NE + 255) / 256, 256>>>(src_ids, dst_ids, times);

    // fused decay + scatter-as-gather (no atomics, no init pass)
    {
        dim3 grid((NN + 7) / 8, 3);
        gather_kernel<<<grid, 256>>>(rp0, rp1, rp2, rp3, times, now_time);
    }

    // pairwise features + MLP (persistent grid, weights in shared)
    {
        int smem = (FF * HH + HH * FF + HH + FF + NW * (HH + FF + 64)) * 4;
        cudaFuncSetAttribute(pair_kernel,
                             cudaFuncAttributeMaxDynamicSharedMemorySize, smem);
        pair_kernel<<<152, NW * 32, smem>>>(rp0, w1, b1, w2, b2,
                                            q_src, q_dst, out);
    }
}